// round 2
// baseline (speedup 1.0000x reference)
#include <cuda_runtime.h>

// Problem constants
#define B_    8
#define K_    8
#define C_    256
#define L_    4096
#define TOPK  4
#define KTOT  (TOPK * C_)   // 1024 — reduction length of the fused per-batch GEMM

// GEMM tiling
#define BM 128
#define BN 128
#define BK 8
#define TM 8
#define TN 8

// Routing results + folded bias (device globals: no allocations allowed)
__device__ int   g_sel[B_][TOPK];
__device__ float g_w[B_][TOPK];
__device__ float g_bias[B_][C_];

// ---------------------------------------------------------------------------
// Prep: per-batch top-4 (ties -> lower index, matching jax.lax.top_k),
// renormalize weights, fold expert_b into a per-(b,d) bias.
// ---------------------------------------------------------------------------
__global__ void prep_kernel(const float* __restrict__ scores,
                            const float* __restrict__ expert_b) {
    __shared__ int   s_sel[B_][TOPK];
    __shared__ float s_w[B_][TOPK];
    const int tid = threadIdx.x;

    if (tid < B_) {
        const int b = tid;
        float sc[K_];
        bool  used[K_];
#pragma unroll
        for (int k = 0; k < K_; k++) { sc[k] = scores[b * K_ + k]; used[k] = false; }
        float sum = 0.f;
#pragma unroll
        for (int j = 0; j < TOPK; j++) {
            int best = 0; float bv = -3.402823466e+38f;
#pragma unroll
            for (int k = 0; k < K_; k++) {
                // strict > keeps the lowest index on ties (jax top_k behavior)
                if (!used[k] && sc[k] > bv) { bv = sc[k]; best = k; }
            }
            used[best] = true;
            s_sel[b][j] = best;
            s_w[b][j]   = bv;
            sum += bv;
        }
        const float inv = 1.f / (sum + 1e-8f);
#pragma unroll
        for (int j = 0; j < TOPK; j++) {
            s_w[b][j] *= inv;
            g_sel[b][j] = s_sel[b][j];
            g_w[b][j]   = s_w[b][j];
        }
    }
    __syncthreads();

    for (int idx = tid; idx < B_ * C_; idx += blockDim.x) {
        const int b = idx / C_, d = idx % C_;
        float acc = 0.f;
#pragma unroll
        for (int j = 0; j < TOPK; j++)
            acc += s_w[b][j] * expert_b[s_sel[b][j] * C_ + d];
        g_bias[b][d] = acc;
    }
}

// ---------------------------------------------------------------------------
// Fused MoE GEMM: out[b] (256x4096) = A_b (256x1024) @ X_b (1024x4096) + bias
//   A_b[d][j*256+c] = w[b,j] * expert_w[sel[b,j]][d][c]   (scaled at SMEM load)
//   X_b[j*256+c][l] = xs[b, sel[b,j], c, l]               (gathered at SMEM load)
// Classic 128x128x8 double-buffered SGEMM, 256 threads, 8x8 per thread.
// ---------------------------------------------------------------------------
__global__ __launch_bounds__(256, 2)
void moe_gemm_kernel(const float* __restrict__ xs,
                     const float* __restrict__ expert_w,
                     float* __restrict__ out) {
    __shared__ float As[2][BK][BM];   // A stored transposed: As[k][m]
    __shared__ float Bs[2][BK][BN];

    const int b   = blockIdx.z;
    const int m0  = blockIdx.y * BM;
    const int n0  = blockIdx.x * BN;
    const int tid = threadIdx.x;

    // A-tile load map: 128 rows x 8 cols, one float4 per thread along K
    const int a_row = tid >> 1;           // 0..127
    const int a_col = (tid & 1) * 4;      // 0 or 4
    // B-tile load map: 8 rows x 128 cols, one float4 per thread along N
    const int b_row = tid >> 5;           // 0..7
    const int b_col = (tid & 31) * 4;     // 0..124

    // Compute map: thread (tx,ty) owns C[ty*8 + i][tx*8 + j]
    const int tx = tid & 15;
    const int ty = tid >> 4;

    int   sel[TOPK];
    float wv[TOPK];
#pragma unroll
    for (int j = 0; j < TOPK; j++) { sel[j] = g_sel[b][j]; wv[j] = g_w[b][j]; }

    float acc[TM][TN];
#pragma unroll
    for (int i = 0; i < TM; i++)
#pragma unroll
        for (int j = 0; j < TN; j++) acc[i][j] = 0.f;

    // ---- prologue: load k0 = 0 into buffer 0 ----
    {
        const int cg = a_col;                 // global reduction index for A
        const int j  = cg >> 8, c = cg & 255;
        const float4 av = *(const float4*)(expert_w +
            ((size_t)sel[j] * C_ + (m0 + a_row)) * C_ + c);
        const float wj = wv[j];
        As[0][a_col + 0][a_row] = av.x * wj;
        As[0][a_col + 1][a_row] = av.y * wj;
        As[0][a_col + 2][a_row] = av.z * wj;
        As[0][a_col + 3][a_row] = av.w * wj;

        const int cgb = b_row;
        const int jb  = cgb >> 8, cb = cgb & 255;
        const float4 bv4 = *(const float4*)(xs +
            (((size_t)b * K_ + sel[jb]) * C_ + cb) * L_ + n0 + b_col);
        *(float4*)&Bs[0][b_row][b_col] = bv4;
    }
    __syncthreads();

    int buf = 0;
    for (int k0 = BK; k0 <= KTOT; k0 += BK) {
        // prefetch next tile into the other buffer
        if (k0 < KTOT) {
            const int nb = buf ^ 1;
            const int cg = k0 + a_col;
            const int j  = cg >> 8, c = cg & 255;
            const float4 av = *(const float4*)(expert_w +
                ((size_t)sel[j] * C_ + (m0 + a_row)) * C_ + c);
            const float wj = wv[j];
            As[nb][a_col + 0][a_row] = av.x * wj;
            As[nb][a_col + 1][a_row] = av.y * wj;
            As[nb][a_col + 2][a_row] = av.z * wj;
            As[nb][a_col + 3][a_row] = av.w * wj;

            const int cgb = k0 + b_row;
            const int jb  = cgb >> 8, cb = cgb & 255;
            const float4 bv4 = *(const float4*)(xs +
                (((size_t)b * K_ + sel[jb]) * C_ + cb) * L_ + n0 + b_col);
            *(float4*)&Bs[nb][b_row][b_col] = bv4;
        }

        // compute on current buffer
#pragma unroll
        for (int kk = 0; kk < BK; kk++) {
            float af[TM], bf[TN];
            const float4 a0 = *(const float4*)&As[buf][kk][ty * TM];
            const float4 a1 = *(const float4*)&As[buf][kk][ty * TM + 4];
            af[0] = a0.x; af[1] = a0.y; af[2] = a0.z; af[3] = a0.w;
            af[4] = a1.x; af[5] = a1.y; af[6] = a1.z; af[7] = a1.w;
            const float4 b0 = *(const float4*)&Bs[buf][kk][tx * TN];
            const float4 b1 = *(const float4*)&Bs[buf][kk][tx * TN + 4];
            bf[0] = b0.x; bf[1] = b0.y; bf[2] = b0.z; bf[3] = b0.w;
            bf[4] = b1.x; bf[5] = b1.y; bf[6] = b1.z; bf[7] = b1.w;
#pragma unroll
            for (int i = 0; i < TM; i++)
#pragma unroll
                for (int j = 0; j < TN; j++)
                    acc[i][j] = fmaf(af[i], bf[j], acc[i][j]);
        }
        __syncthreads();
        buf ^= 1;
    }

    // ---- epilogue: + bias, write out ----
#pragma unroll
    for (int i = 0; i < TM; i++) {
        const int d = m0 + ty * TM + i;
        const float bias = g_bias[b][d];
        float* op = out + ((size_t)b * C_ + d) * L_ + n0 + tx * TN;
        float4 v0, v1;
        v0.x = acc[i][0] + bias; v0.y = acc[i][1] + bias;
        v0.z = acc[i][2] + bias; v0.w = acc[i][3] + bias;
        v1.x = acc[i][4] + bias; v1.y = acc[i][5] + bias;
        v1.z = acc[i][6] + bias; v1.w = acc[i][7] + bias;
        *(float4*)(op)     = v0;
        *(float4*)(op + 4) = v1;
    }
}

// ---------------------------------------------------------------------------
// Launch: inputs in metadata order: xs, scores, expert_w, expert_b
// ---------------------------------------------------------------------------
extern "C" void kernel_launch(void* const* d_in, const int* in_sizes, int n_in,
                              void* d_out, int out_size) {
    const float* xs       = (const float*)d_in[0];
    const float* scores   = (const float*)d_in[1];
    const float* expert_w = (const float*)d_in[2];
    const float* expert_b = (const float*)d_in[3];
    float* out = (float*)d_out;

    prep_kernel<<<1, 256>>>(scores, expert_b);

    dim3 grid(L_ / BN, C_ / BM, B_);   // (32, 2, 8) = 512 blocks
    moe_gemm_kernel<<<grid, 256>>>(xs, expert_w, out);
}

// round 4
// speedup vs baseline: 2.0463x; 2.0463x over previous
#include <cuda_runtime.h>
#include <cstdint>

// ---------------- problem constants ----------------
#define B_    8
#define K_    8
#define C_    256
#define L_    4096
#define TOPK  4
#define KTOT  1024
#define BM    128
#define BN    128
#define BK    32
#define NCHUNK (KTOT / BK)     // 32

// ---------------- smem layout (bytes from dynamic smem base) ----------------
// A tiles: 128 rows x 32 bf16, padded row stride 40 bf16 = 80 B (5x16B, odd -> ldmatrix conflict-free)
// B tiles: 32 rows (k) x 128 bf16 (n), padded stride 136 bf16 = 272 B (17x16B, odd)
#define ASTRIDE_B 80
#define BSTRIDE_B 272
#define ATILE_B   (128 * ASTRIDE_B)          // 10240
#define BTILE_B   (32 * BSTRIDE_B)           // 8704
#define BUF_B     (2 * ATILE_B + 2 * BTILE_B) // 37888
#define OFF_AHI(buf) ((buf) * BUF_B + 0)
#define OFF_ALO(buf) ((buf) * BUF_B + ATILE_B)
#define OFF_BHI(buf) ((buf) * BUF_B + 2 * ATILE_B)
#define OFF_BLO(buf) ((buf) * BUF_B + 2 * ATILE_B + BTILE_B)
#define SMEM_DYN  (2 * BUF_B)                 // 75776

// ---------------- helpers ----------------
__device__ __forceinline__ uint32_t smem_u32(const void* p) {
    uint32_t a;
    asm("{ .reg .u64 t; cvta.to.shared.u64 t, %1; cvt.u32.u64 %0, t; }" : "=r"(a) : "l"(p));
    return a;
}

// split x -> (hi = truncate-to-bf16, lo = rn-bf16(x - hi)); pack two elements
__device__ __forceinline__ void split_pair(float x0, float x1,
                                           uint32_t& hi, uint32_t& lo) {
    uint32_t u0 = __float_as_uint(x0), u1 = __float_as_uint(x1);
    hi = __byte_perm(u0, u1, 0x7632);   // {bf16(x1)|bf16(x0)} truncated
    float l0 = x0 - __uint_as_float(u0 & 0xFFFF0000u);
    float l1 = x1 - __uint_as_float(u1 & 0xFFFF0000u);
    asm("cvt.rn.bf16x2.f32 %0, %1, %2;" : "=r"(lo) : "f"(l1), "f"(l0));
}

#define STS64(addr, r0, r1) \
    asm volatile("st.shared.v2.b32 [%0], {%1, %2};" :: "r"(addr), "r"(r0), "r"(r1) : "memory")

__device__ __forceinline__ void ldsm_x4(uint32_t addr, uint32_t* r) {
    asm volatile("ldmatrix.sync.aligned.m8n8.x4.shared.b16 {%0,%1,%2,%3}, [%4];"
                 : "=r"(r[0]), "=r"(r[1]), "=r"(r[2]), "=r"(r[3]) : "r"(addr));
}
__device__ __forceinline__ void ldsm_x2_trans(uint32_t addr, uint32_t* r) {
    asm volatile("ldmatrix.sync.aligned.m8n8.x2.trans.shared.b16 {%0,%1}, [%2];"
                 : "=r"(r[0]), "=r"(r[1]) : "r"(addr));
}
__device__ __forceinline__ void mma_bf16(float* c, const uint32_t* a, const uint32_t* bfr) {
    asm volatile(
        "mma.sync.aligned.m16n8k16.row.col.f32.bf16.bf16.f32 "
        "{%0,%1,%2,%3}, {%4,%5,%6,%7}, {%8,%9}, {%0,%1,%2,%3};"
        : "+f"(c[0]), "+f"(c[1]), "+f"(c[2]), "+f"(c[3])
        : "r"(a[0]), "r"(a[1]), "r"(a[2]), "r"(a[3]), "r"(bfr[0]), "r"(bfr[1]));
}

// ---------------- routing globals ----------------
__device__ int   g_sel[B_][TOPK];
__device__ float g_w[B_][TOPK];
__device__ float g_bias[B_][C_];

__global__ void prep_kernel(const float* __restrict__ scores,
                            const float* __restrict__ expert_b) {
    __shared__ int   s_sel[B_][TOPK];
    __shared__ float s_w[B_][TOPK];
    const int tid = threadIdx.x;
    if (tid < B_) {
        const int b = tid;
        float sc[K_]; bool used[K_];
#pragma unroll
        for (int k = 0; k < K_; k++) { sc[k] = scores[b * K_ + k]; used[k] = false; }
        float sum = 0.f;
#pragma unroll
        for (int j = 0; j < TOPK; j++) {
            int best = 0; float bv = -3.402823466e+38f;
#pragma unroll
            for (int k = 0; k < K_; k++)
                if (!used[k] && sc[k] > bv) { bv = sc[k]; best = k; }  // ties -> lower idx
            used[best] = true; s_sel[b][j] = best; s_w[b][j] = bv; sum += bv;
        }
        const float inv = 1.f / (sum + 1e-8f);
#pragma unroll
        for (int j = 0; j < TOPK; j++) {
            s_w[b][j] *= inv; g_sel[b][j] = s_sel[b][j]; g_w[b][j] = s_w[b][j];
        }
    }
    __syncthreads();
    for (int idx = tid; idx < B_ * C_; idx += blockDim.x) {
        const int b = idx / C_, d = idx % C_;
        float acc = 0.f;
#pragma unroll
        for (int j = 0; j < TOPK; j++)
            acc += s_w[b][j] * expert_b[s_sel[b][j] * C_ + d];
        g_bias[b][d] = acc;
    }
}

// ---------------------------------------------------------------------------
// Tensor-core MoE GEMM via mma.sync (bf16 hi/lo split, 3 terms, fp32 accum):
// out[b](256x4096) = [w_j * W_sel_j](256x1024) @ gathered_xs(1024x4096) + bias
// ---------------------------------------------------------------------------
__global__ __launch_bounds__(256, 1)
void moe_mma_kernel(const float* __restrict__ xs,
                    const float* __restrict__ expert_w,
                    float* __restrict__ out) {
    extern __shared__ char smem[];
    const uint32_t sb = smem_u32(smem);

    const int tid  = threadIdx.x;
    const int wid  = tid >> 5;
    const int lane = tid & 31;
    const int b    = blockIdx.z;
    const int m0   = blockIdx.y * BM;
    const int n0   = blockIdx.x * BN;

    int   sel[TOPK];
    float wv[TOPK];
#pragma unroll
    for (int j = 0; j < TOPK; j++) { sel[j] = g_sel[b][j]; wv[j] = g_w[b][j]; }

    // warp tile: 64 (m) x 32 (n)
    const int wm = wid >> 2, wn = wid & 3;
    const int m_base = wm * 64, n_base = wn * 32;

    float acc[4][4][4];
#pragma unroll
    for (int mi = 0; mi < 4; mi++)
#pragma unroll
        for (int ni = 0; ni < 4; ni++)
#pragma unroll
            for (int r = 0; r < 4; r++) acc[mi][ni][r] = 0.f;

    // ldmatrix address components (canonical m16n8k16 pattern)
    const int lr = lane & 7;
    const int lg = lane >> 3;              // 0..3
    const int a_r_off = (lg & 1) * 8 + lr; // row within 16
    const int a_c_off = (lg >> 1) * 8;     // k-col 0 or 8
    const int b_r_off = (lg & 1) * 8 + lr; // k-row for x2 (lanes 16-31 mirror 0-15; addrs ignored)

    // global load maps
    const int a_row = tid >> 1;            // not used; loads are f-indexed below

    // ---- chunk load+convert+store into buffer `buf` ----
    auto stage_chunk = [&](int ck, int buf) {
        const int j  = ck >> 3;
        const int c0 = (ck & 7) * BK;
        const float wj = wv[j];
        const float* asrc = expert_w + ((size_t)sel[j] * C_) * C_ + c0;
        const float* bsrc = xs + (((size_t)b * K_ + sel[j]) * C_ + c0) * L_ + n0;
        const uint32_t ah = sb + OFF_AHI(buf), al = sb + OFF_ALO(buf);
        const uint32_t bh = sb + OFF_BHI(buf), bl = sb + OFF_BLO(buf);

        float4 av[4], bv[4];
#pragma unroll
        for (int q = 0; q < 4; q++) {
            int f = q * 256 + tid;              // 0..1023
            int r = f >> 3, c4 = f & 7;         // A: 128 rows x 8 f4
            av[q] = *(const float4*)(asrc + (size_t)(m0 + r) * C_ + c4 * 4);
        }
#pragma unroll
        for (int q = 0; q < 4; q++) {
            int f = q * 256 + tid;
            int r = f >> 5, c4 = f & 31;        // B: 32 rows x 32 f4
            bv[q] = *(const float4*)(bsrc + (size_t)r * L_ + c4 * 4);
        }
#pragma unroll
        for (int q = 0; q < 4; q++) {
            int f = q * 256 + tid;
            int r = f >> 3, c4 = f & 7;
            uint32_t h0, l0, h1, l1;
            split_pair(av[q].x * wj, av[q].y * wj, h0, l0);
            split_pair(av[q].z * wj, av[q].w * wj, h1, l1);
            uint32_t addr = r * ASTRIDE_B + c4 * 8;
            STS64(ah + addr, h0, h1);
            STS64(al + addr, l0, l1);
        }
#pragma unroll
        for (int q = 0; q < 4; q++) {
            int f = q * 256 + tid;
            int r = f >> 5, c4 = f & 31;
            uint32_t h0, l0, h1, l1;
            split_pair(bv[q].x, bv[q].y, h0, l0);
            split_pair(bv[q].z, bv[q].w, h1, l1);
            uint32_t addr = r * BSTRIDE_B + c4 * 8;
            STS64(bh + addr, h0, h1);
            STS64(bl + addr, l0, l1);
        }
    };

    stage_chunk(0, 0);
    __syncthreads();

    for (int ck = 0; ck < NCHUNK; ck++) {
        const int buf = ck & 1;
        const uint32_t ah = sb + OFF_AHI(buf), al = sb + OFF_ALO(buf);
        const uint32_t bh = sb + OFF_BHI(buf), bl = sb + OFF_BLO(buf);

#pragma unroll
        for (int ks = 0; ks < 2; ks++) {
            const int k0 = ks * 16;
            uint32_t Ah[4][4], Al[4][4], Bh[4][2], Bl[4][2];
#pragma unroll
            for (int mi = 0; mi < 4; mi++) {
                uint32_t addr = (m_base + mi * 16 + a_r_off) * ASTRIDE_B
                              + (k0 + a_c_off) * 2;
                ldsm_x4(ah + addr, Ah[mi]);
                ldsm_x4(al + addr, Al[mi]);
            }
#pragma unroll
            for (int ni = 0; ni < 4; ni++) {
                uint32_t addr = (k0 + b_r_off) * BSTRIDE_B
                              + (n_base + ni * 8) * 2;
                ldsm_x2_trans(bh + addr, Bh[ni]);
                ldsm_x2_trans(bl + addr, Bl[ni]);
            }
#pragma unroll
            for (int mi = 0; mi < 4; mi++)
#pragma unroll
                for (int ni = 0; ni < 4; ni++) {
                    mma_bf16(acc[mi][ni], Ah[mi], Bh[ni]);
                    mma_bf16(acc[mi][ni], Ah[mi], Bl[ni]);
                    mma_bf16(acc[mi][ni], Al[mi], Bh[ni]);
                }
        }
        __syncthreads();            // everyone done reading buf before overwrite
        if (ck + 1 < NCHUNK) {
            stage_chunk(ck + 1, buf ^ 1);
            __syncthreads();
        }
    }

    // ---- epilogue: + bias, write ----
    const int g  = lane >> 2;       // 0..7
    const int tq = lane & 3;        // 0..3
#pragma unroll
    for (int mi = 0; mi < 4; mi++) {
        const int r0 = m0 + m_base + mi * 16 + g;
        const int r1 = r0 + 8;
        const float bias0 = g_bias[b][r0];
        const float bias1 = g_bias[b][r1];
        float* p0 = out + ((size_t)b * C_ + r0) * L_ + n0 + n_base + tq * 2;
        float* p1 = out + ((size_t)b * C_ + r1) * L_ + n0 + n_base + tq * 2;
#pragma unroll
        for (int ni = 0; ni < 4; ni++) {
            float2 v0 = make_float2(acc[mi][ni][0] + bias0, acc[mi][ni][1] + bias0);
            float2 v1 = make_float2(acc[mi][ni][2] + bias1, acc[mi][ni][3] + bias1);
            *(float2*)(p0 + ni * 8) = v0;
            *(float2*)(p1 + ni * 8) = v1;
        }
    }
}

// ---------------- launch ----------------
extern "C" void kernel_launch(void* const* d_in, const int* in_sizes, int n_in,
                              void* d_out, int out_size) {
    const float* xs       = (const float*)d_in[0];
    const float* scores   = (const float*)d_in[1];
    const float* expert_w = (const float*)d_in[2];
    const float* expert_b = (const float*)d_in[3];
    float* out = (float*)d_out;

    cudaFuncSetAttribute(moe_mma_kernel,
                         cudaFuncAttributeMaxDynamicSharedMemorySize, SMEM_DYN);

    prep_kernel<<<1, 256>>>(scores, expert_b);

    dim3 grid(L_ / BN, C_ / BM, B_);   // (32, 2, 8) = 512 blocks
    moe_mma_kernel<<<grid, 256, SMEM_DYN>>>(xs, expert_w, out);
}